// round 1
// baseline (speedup 1.0000x reference)
#include <cuda_runtime.h>
#include <math.h>

#define BB 4
#define TT 4096
#define DD 1024
#define HD 64

// Scratch for projected Q, K, V (4 MB each). Static __device__ arrays: allowed.
__device__ float g_Q[BB * TT * HD];
__device__ float g_K[BB * TT * HD];
__device__ float g_V[BB * TT * HD];

// ---------------------------------------------------------------------------
// Kernel 1: fused QKV projection.  out[m,n] = sum_k x[m,k] * w[n,k]
// M = B*T = 16384, K = 1024, N = 64 per weight. blockIdx.y selects wq/wk/wv.
// 64x64 block tile, 4x4 register micro-tile per thread, BK=16.
// Smem tiles stored transposed ([k][m], [k][n]) for conflict-light float4 reads.
// ---------------------------------------------------------------------------
__global__ __launch_bounds__(256) void qkv_kernel(
    const float* __restrict__ x,
    const float* __restrict__ wq,
    const float* __restrict__ wk,
    const float* __restrict__ wv)
{
    __shared__ float xs[16][64];  // [k][m]
    __shared__ float ws[16][64];  // [k][n]

    const int tid   = threadIdx.x;
    const int which = blockIdx.y;
    const float* __restrict__ w    = (which == 0) ? wq  : (which == 1) ? wk  : wv;
    float*       __restrict__ outp = (which == 0) ? g_Q : (which == 1) ? g_K : g_V;

    const int m0 = blockIdx.x * 64;
    const int lr = tid & 63;          // load row (m or n), 0..63
    const int lk = (tid >> 6) * 4;    // load k offset: 0,4,8,12
    const int r0 = (tid >> 4) * 4;    // compute rows (m)
    const int c0 = (tid & 15) * 4;    // compute cols (n)

    float acc[4][4] = {};

    for (int k0 = 0; k0 < DD; k0 += 16) {
        float4 xv  = *(const float4*)(x + (m0 + lr) * DD + k0 + lk);
        float4 wv4 = *(const float4*)(w + lr * DD + k0 + lk);
        __syncthreads();  // previous iteration's compute reads complete
        xs[lk + 0][lr] = xv.x;  xs[lk + 1][lr] = xv.y;
        xs[lk + 2][lr] = xv.z;  xs[lk + 3][lr] = xv.w;
        ws[lk + 0][lr] = wv4.x; ws[lk + 1][lr] = wv4.y;
        ws[lk + 2][lr] = wv4.z; ws[lk + 3][lr] = wv4.w;
        __syncthreads();

        #pragma unroll
        for (int k = 0; k < 16; k++) {
            float4 a = *(const float4*)&xs[k][r0];
            float4 b = *(const float4*)&ws[k][c0];
            float av[4] = {a.x, a.y, a.z, a.w};
            float bv[4] = {b.x, b.y, b.z, b.w};
            #pragma unroll
            for (int i = 0; i < 4; i++)
                #pragma unroll
                for (int j = 0; j < 4; j++)
                    acc[i][j] = fmaf(av[i], bv[j], acc[i][j]);
        }
    }

    #pragma unroll
    for (int i = 0; i < 4; i++) {
        float4 o = make_float4(acc[i][0], acc[i][1], acc[i][2], acc[i][3]);
        *(float4*)(outp + (m0 + r0 + i) * HD + c0) = o;
    }
}

// ---------------------------------------------------------------------------
// Kernel 2: flash attention, fp32, full (non-causal) softmax over T=4096.
// Grid: (T/64, B). Block: 256 threads.
// Per block: 64 query rows, loop over 64-key tiles with online softmax.
// Thread (tid): owns rows r0..r0+3 where r0=(tid>>4)*4 (shared by the 16
// lanes of a warp-half -> shfl row reductions), cols/dims c0..c0+3.
// Smem: Qt [d][r], KP (Kt [d][c], reused as P [r][c]), Vs [s][d] = 48KB.
// ---------------------------------------------------------------------------
__global__ __launch_bounds__(256) void attn_kernel(float* __restrict__ out)
{
    __shared__ float Qt[64][64];  // [d][r], pre-scaled by 1/sqrt(HD)
    __shared__ float KP[64][64];  // phase 1: K^T [d][c]; phase 2: P [r][c]
    __shared__ float Vs[64][64];  // [s][d]

    const int tid = threadIdx.x;
    const int b   = blockIdx.y;
    const int t0  = blockIdx.x * 64;
    const int lr  = tid & 63;
    const int lk  = (tid >> 6) * 4;
    const int r0  = (tid >> 4) * 4;  // same for 16 consecutive lanes (warp half)
    const int c0  = (tid & 15) * 4;

    // Load Q tile, transposed + pre-scaled
    const float* qb = g_Q + (b * TT + t0) * HD;
    #pragma unroll
    for (int it = 0; it < 4; it++) {
        int d = lk + it * 16;
        float4 v = *(const float4*)(qb + lr * HD + d);
        Qt[d + 0][lr] = v.x * 0.125f;
        Qt[d + 1][lr] = v.y * 0.125f;
        Qt[d + 2][lr] = v.z * 0.125f;
        Qt[d + 3][lr] = v.w * 0.125f;
    }

    float m_i[4], l_i[4], o[4][4];
    #pragma unroll
    for (int i = 0; i < 4; i++) {
        m_i[i] = -INFINITY;
        l_i[i] = 0.0f;
        #pragma unroll
        for (int j = 0; j < 4; j++) o[i][j] = 0.0f;
    }

    for (int s0 = 0; s0 < TT; s0 += 64) {
        const float* kb = g_K + (b * TT + s0) * HD;
        const float* vb = g_V + (b * TT + s0) * HD;

        __syncthreads();  // prior tile's PV reads (and initial Qt writes) done
        #pragma unroll
        for (int it = 0; it < 4; it++) {
            int d = lk + it * 16;
            float4 v = *(const float4*)(kb + lr * HD + d);
            KP[d + 0][lr] = v.x; KP[d + 1][lr] = v.y;
            KP[d + 2][lr] = v.z; KP[d + 3][lr] = v.w;
            int off = it * 1024 + tid * 4;
            *(float4*)(&Vs[0][0] + off) = *(const float4*)(vb + off);
        }
        __syncthreads();

        // S = (Q/8) @ K^T  -> 4x4 per thread
        float s_[4][4] = {};
        #pragma unroll 8
        for (int d = 0; d < 64; d++) {
            float4 a  = *(const float4*)&Qt[d][r0];
            float4 bb = *(const float4*)&KP[d][c0];
            float av[4] = {a.x, a.y, a.z, a.w};
            float bv[4] = {bb.x, bb.y, bb.z, bb.w};
            #pragma unroll
            for (int i = 0; i < 4; i++)
                #pragma unroll
                for (int j = 0; j < 4; j++)
                    s_[i][j] = fmaf(av[i], bv[j], s_[i][j]);
        }

        // Online softmax (registers + 16-lane shfl row reductions)
        float alpha[4];
        #pragma unroll
        for (int i = 0; i < 4; i++) {
            float tm = fmaxf(fmaxf(s_[i][0], s_[i][1]), fmaxf(s_[i][2], s_[i][3]));
            #pragma unroll
            for (int off = 8; off > 0; off >>= 1)
                tm = fmaxf(tm, __shfl_xor_sync(0xffffffffu, tm, off));
            float mnew = fmaxf(m_i[i], tm);
            alpha[i] = __expf(m_i[i] - mnew);
            float rs = 0.0f;
            #pragma unroll
            for (int j = 0; j < 4; j++) {
                s_[i][j] = __expf(s_[i][j] - mnew);
                rs += s_[i][j];
            }
            #pragma unroll
            for (int off = 8; off > 0; off >>= 1)
                rs += __shfl_xor_sync(0xffffffffu, rs, off);
            l_i[i] = l_i[i] * alpha[i] + rs;
            m_i[i] = mnew;
            #pragma unroll
            for (int j = 0; j < 4; j++) o[i][j] *= alpha[i];
        }

        __syncthreads();  // all K^T reads done -> safe to overwrite KP with P
        #pragma unroll
        for (int i = 0; i < 4; i++)
            *(float4*)&KP[r0 + i][c0] =
                make_float4(s_[i][0], s_[i][1], s_[i][2], s_[i][3]);
        __syncthreads();

        // O += P @ V   (dims owned per-thread = c0..c0+3)
        #pragma unroll 4
        for (int c4 = 0; c4 < 64; c4 += 4) {
            float4 ar[4];
            #pragma unroll
            for (int i = 0; i < 4; i++)
                ar[i] = *(const float4*)&KP[r0 + i][c4];  // broadcast in warp-half
            float a_[4][4] = {
                {ar[0].x, ar[0].y, ar[0].z, ar[0].w},
                {ar[1].x, ar[1].y, ar[1].z, ar[1].w},
                {ar[2].x, ar[2].y, ar[2].z, ar[2].w},
                {ar[3].x, ar[3].y, ar[3].z, ar[3].w}};
            #pragma unroll
            for (int cc = 0; cc < 4; cc++) {
                float4 v = *(const float4*)&Vs[c4 + cc][c0];
                float vv[4] = {v.x, v.y, v.z, v.w};
                #pragma unroll
                for (int i = 0; i < 4; i++)
                    #pragma unroll
                    for (int j = 0; j < 4; j++)
                        o[i][j] = fmaf(a_[i][cc], vv[j], o[i][j]);
            }
        }
    }

    // Normalize + write
    float* ob = out + (b * TT + t0) * HD;
    #pragma unroll
    for (int i = 0; i < 4; i++) {
        float inv = 1.0f / l_i[i];
        float4 ov = make_float4(o[i][0] * inv, o[i][1] * inv,
                                o[i][2] * inv, o[i][3] * inv);
        *(float4*)(ob + (r0 + i) * HD + c0) = ov;
    }
}

extern "C" void kernel_launch(void* const* d_in, const int* in_sizes, int n_in,
                              void* d_out, int out_size)
{
    const float* x  = (const float*)d_in[0];
    const float* wq = (const float*)d_in[1];
    const float* wk = (const float*)d_in[2];
    const float* wv = (const float*)d_in[3];
    float* out = (float*)d_out;

    qkv_kernel<<<dim3((BB * TT) / 64, 3), 256>>>(x, wq, wk, wv);
    attn_kernel<<<dim3(TT / 64, BB), 256>>>(out);
}

// round 2
// speedup vs baseline: 3.5061x; 3.5061x over previous
#include <cuda_runtime.h>
#include <math.h>
#include <stdint.h>

#define BB 4
#define TT 4096
#define DD 1024
#define HD 64

#define TM 128   // q rows per block (attention)
#define TN 128   // keys per tile
#define PS 132   // P smem stride (floats)  132%32=4 -> conflict-free frags
#define KS 68    // K smem stride            68%32=4
#define VS 72    // V smem stride            72%32=8
#define XS 36    // projection smem stride   36%32=4

// Scratch for projected Q, K, V.
__device__ float g_Q[BB * TT * HD];
__device__ float g_K[BB * TT * HD];
__device__ float g_V[BB * TT * HD];

// fp32 -> tf32 (round-to-nearest) kept in a 32-bit container
__device__ __forceinline__ uint32_t f2tf32(float x) {
    uint32_t r;
    asm("cvt.rna.tf32.f32 %0, %1;" : "=r"(r) : "f"(x));
    return r;
}
__device__ __forceinline__ float tf(float x) { return __uint_as_float(f2tf32(x)); }

// D += A(16x8,row) * B(8x8,col); tf32 inputs, f32 accum
__device__ __forceinline__ void mma_tf32(float d[4], uint32_t a0, uint32_t a1,
                                         uint32_t a2, uint32_t a3,
                                         uint32_t b0, uint32_t b1) {
    asm("mma.sync.aligned.m16n8k8.row.col.f32.tf32.tf32.f32 "
        "{%0,%1,%2,%3}, {%4,%5,%6,%7}, {%8,%9}, {%0,%1,%2,%3};"
        : "+f"(d[0]), "+f"(d[1]), "+f"(d[2]), "+f"(d[3])
        : "r"(a0), "r"(a1), "r"(a2), "r"(a3), "r"(b0), "r"(b1));
}

// ---------------------------------------------------------------------------
// QKV projection: out[m][n] = sum_k x[m][k] * w[n][k].  M=16384, N=64, K=1024.
// Grid (128, 3); block 256 (8 warps). Warp w owns rows 16w..16w+15.
// ---------------------------------------------------------------------------
__global__ __launch_bounds__(256) void qkv_tc(
    const float* __restrict__ x,
    const float* __restrict__ wq,
    const float* __restrict__ wk,
    const float* __restrict__ wv)
{
    __shared__ float xs[TM * XS];      // 128 x 32 (padded)
    __shared__ float wsm[HD * XS];     // 64 x 32 (padded)

    const int tid  = threadIdx.x;
    const int w    = tid >> 5;
    const int lane = tid & 31;
    const int g    = lane >> 2;   // 0..7
    const int c    = lane & 3;    // 0..3

    const int which = blockIdx.y;
    const float* __restrict__ wp   = (which == 0) ? wq  : (which == 1) ? wk  : wv;
    float*       __restrict__ outp = (which == 0) ? g_Q : (which == 1) ? g_K : g_V;

    const int m0 = blockIdx.x * TM;

    float o[8][4];
    #pragma unroll
    for (int ni = 0; ni < 8; ni++)
        #pragma unroll
        for (int j = 0; j < 4; j++) o[ni][j] = 0.0f;

    for (int k0 = 0; k0 < DD; k0 += 32) {
        __syncthreads();
        // load x tile 128x32 (1024 float4)
        #pragma unroll
        for (int i = 0; i < 4; i++) {
            int idx = tid + i * 256;
            int row = idx >> 3, c4 = (idx & 7) << 2;
            float4 v = *(const float4*)(x + (m0 + row) * DD + k0 + c4);
            *(float4*)(xs + row * XS + c4) =
                make_float4(tf(v.x), tf(v.y), tf(v.z), tf(v.w));
        }
        // load w tile 64x32 (512 float4)
        #pragma unroll
        for (int i = 0; i < 2; i++) {
            int idx = tid + i * 256;
            int row = idx >> 3, c4 = (idx & 7) << 2;
            float4 v = *(const float4*)(wp + row * DD + k0 + c4);
            *(float4*)(wsm + row * XS + c4) =
                make_float4(tf(v.x), tf(v.y), tf(v.z), tf(v.w));
        }
        __syncthreads();

        #pragma unroll
        for (int kc = 0; kc < 4; kc++) {
            const float* ar = xs + (16 * w + g) * XS + 8 * kc + c;
            uint32_t a0 = __float_as_uint(ar[0]);
            uint32_t a1 = __float_as_uint(ar[8 * XS]);
            uint32_t a2 = __float_as_uint(ar[4]);
            uint32_t a3 = __float_as_uint(ar[8 * XS + 4]);
            const float* br = wsm + g * XS + 8 * kc + c;
            #pragma unroll
            for (int ni = 0; ni < 8; ni++) {
                uint32_t b0 = __float_as_uint(br[8 * ni * XS]);
                uint32_t b1 = __float_as_uint(br[8 * ni * XS + 4]);
                mma_tf32(o[ni], a0, a1, a2, a3, b0, b1);
            }
        }
    }

    float* ob = outp + (m0 + 16 * w) * HD;
    #pragma unroll
    for (int ni = 0; ni < 8; ni++) {
        int col = 8 * ni + 2 * c;
        *(float2*)(ob + g * HD + col)       = make_float2(o[ni][0], o[ni][1]);
        *(float2*)(ob + (g + 8) * HD + col) = make_float2(o[ni][2], o[ni][3]);
    }
}

// ---------------------------------------------------------------------------
// Flash attention, tf32 tensor cores. Grid (T/128, B) = 128 blocks, 256 thr.
// Warp w owns q rows 16w..16w+15 (full rows -> warp-local softmax).
// Smem: union(P[128][132] / K[128][68]) + V[128][72] = 104448 B dynamic.
// ---------------------------------------------------------------------------
__global__ void __launch_bounds__(256) attn_tc(float* __restrict__ out)
{
    extern __shared__ float sm[];
    float* Pbuf = sm;              // 128*132, aliases Kbuf
    float* Kbuf = sm;              // 128*68
    float* Vbuf = sm + TM * PS;    // 128*72

    const int tid  = threadIdx.x;
    const int w    = tid >> 5;
    const int lane = tid & 31;
    const int g    = lane >> 2;
    const int c    = lane & 3;

    const int b  = blockIdx.y;
    const int t0 = blockIdx.x * TM;

    // Preload Q fragments (scaled by 1/sqrt(HD)=0.125), tf32
    uint32_t qa[8][4];
    const float* qb = g_Q + (b * TT + t0 + 16 * w) * HD;
    #pragma unroll
    for (int ks = 0; ks < 8; ks++) {
        int col = 8 * ks + c;
        qa[ks][0] = f2tf32(qb[g * HD + col] * 0.125f);
        qa[ks][1] = f2tf32(qb[(g + 8) * HD + col] * 0.125f);
        qa[ks][2] = f2tf32(qb[g * HD + col + 4] * 0.125f);
        qa[ks][3] = f2tf32(qb[(g + 8) * HD + col + 4] * 0.125f);
    }

    float m0r = -INFINITY, m1r = -INFINITY, l0 = 0.0f, l1 = 0.0f;
    float o[8][4];
    #pragma unroll
    for (int ni = 0; ni < 8; ni++)
        #pragma unroll
        for (int j = 0; j < 4; j++) o[ni][j] = 0.0f;

    for (int s0 = 0; s0 < TT; s0 += TN) {
        const float* kg = g_K + (b * TT + s0) * HD;
        const float* vg = g_V + (b * TT + s0) * HD;

        __syncthreads();  // previous tile's PV reads of P/V complete
        #pragma unroll
        for (int i = 0; i < 8; i++) {
            int idx = tid + i * 256;          // 0..2047
            int row = idx >> 4, c4 = (idx & 15) << 2;
            float4 kv = *(const float4*)(kg + row * HD + c4);
            float4 vv = *(const float4*)(vg + row * HD + c4);
            *(float4*)(Kbuf + row * KS + c4) =
                make_float4(tf(kv.x), tf(kv.y), tf(kv.z), tf(kv.w));
            *(float4*)(Vbuf + row * VS + c4) =
                make_float4(tf(vv.x), tf(vv.y), tf(vv.z), tf(vv.w));
        }
        __syncthreads();

        // S = Q @ K^T : per warp 16 x 128
        float s_[16][4];
        #pragma unroll
        for (int ni = 0; ni < 16; ni++) {
            s_[ni][0] = s_[ni][1] = s_[ni][2] = s_[ni][3] = 0.0f;
            const float* kr = Kbuf + (8 * ni + g) * KS + c;
            #pragma unroll
            for (int ks = 0; ks < 8; ks++) {
                uint32_t b0 = __float_as_uint(kr[8 * ks]);
                uint32_t b1 = __float_as_uint(kr[8 * ks + 4]);
                mma_tf32(s_[ni], qa[ks][0], qa[ks][1], qa[ks][2], qa[ks][3], b0, b1);
            }
        }

        // online softmax (rows g and g+8, quad-shfl reductions)
        float rx0 = -INFINITY, rx1 = -INFINITY;
        #pragma unroll
        for (int ni = 0; ni < 16; ni++) {
            rx0 = fmaxf(rx0, fmaxf(s_[ni][0], s_[ni][1]));
            rx1 = fmaxf(rx1, fmaxf(s_[ni][2], s_[ni][3]));
        }
        rx0 = fmaxf(rx0, __shfl_xor_sync(0xffffffffu, rx0, 1));
        rx0 = fmaxf(rx0, __shfl_xor_sync(0xffffffffu, rx0, 2));
        rx1 = fmaxf(rx1, __shfl_xor_sync(0xffffffffu, rx1, 1));
        rx1 = fmaxf(rx1, __shfl_xor_sync(0xffffffffu, rx1, 2));
        float mn0 = fmaxf(m0r, rx0), mn1 = fmaxf(m1r, rx1);
        float al0 = __expf(m0r - mn0), al1 = __expf(m1r - mn1);
        m0r = mn0; m1r = mn1;
        float rs0 = 0.0f, rs1 = 0.0f;
        #pragma unroll
        for (int ni = 0; ni < 16; ni++) {
            s_[ni][0] = __expf(s_[ni][0] - mn0);
            s_[ni][1] = __expf(s_[ni][1] - mn0);
            s_[ni][2] = __expf(s_[ni][2] - mn1);
            s_[ni][3] = __expf(s_[ni][3] - mn1);
            rs0 += s_[ni][0] + s_[ni][1];
            rs1 += s_[ni][2] + s_[ni][3];
        }
        rs0 += __shfl_xor_sync(0xffffffffu, rs0, 1);
        rs0 += __shfl_xor_sync(0xffffffffu, rs0, 2);
        rs1 += __shfl_xor_sync(0xffffffffu, rs1, 1);
        rs1 += __shfl_xor_sync(0xffffffffu, rs1, 2);
        l0 = l0 * al0 + rs0;
        l1 = l1 * al1 + rs1;
        #pragma unroll
        for (int ni = 0; ni < 8; ni++) {
            o[ni][0] *= al0; o[ni][1] *= al0;
            o[ni][2] *= al1; o[ni][3] *= al1;
        }

        __syncthreads();  // all warps done reading Kbuf -> safe to write Pbuf
        float* pr0 = Pbuf + (16 * w + g) * PS + 2 * c;
        float* pr1 = pr0 + 8 * PS;
        #pragma unroll
        for (int ni = 0; ni < 16; ni++) {
            *(float2*)(pr0 + 8 * ni) = make_float2(tf(s_[ni][0]), tf(s_[ni][1]));
            *(float2*)(pr1 + 8 * ni) = make_float2(tf(s_[ni][2]), tf(s_[ni][3]));
        }
        __syncwarp();  // warp reads only its own rows

        // O += P @ V : per warp 16 x 64, K-dim = 128 keys
        #pragma unroll
        for (int ki = 0; ki < 16; ki++) {
            const float* pa = Pbuf + (16 * w + g) * PS + 8 * ki + c;
            uint32_t a0 = __float_as_uint(pa[0]);
            uint32_t a1 = __float_as_uint(pa[8 * PS]);
            uint32_t a2 = __float_as_uint(pa[4]);
            uint32_t a3 = __float_as_uint(pa[8 * PS + 4]);
            const float* vr = Vbuf + (8 * ki + c) * VS + g;
            #pragma unroll
            for (int ni = 0; ni < 8; ni++) {
                uint32_t b0 = __float_as_uint(vr[8 * ni]);
                uint32_t b1 = __float_as_uint(vr[8 * ni + 4 * VS]);
                mma_tf32(o[ni], a0, a1, a2, a3, b0, b1);
            }
        }
    }

    float inv0 = 1.0f / l0, inv1 = 1.0f / l1;
    float* ob = out + (b * TT + t0 + 16 * w) * HD;
    #pragma unroll
    for (int ni = 0; ni < 8; ni++) {
        int col = 8 * ni + 2 * c;
        *(float2*)(ob + g * HD + col) =
            make_float2(o[ni][0] * inv0, o[ni][1] * inv0);
        *(float2*)(ob + (g + 8) * HD + col) =
            make_float2(o[ni][2] * inv1, o[ni][3] * inv1);
    }
}

extern "C" void kernel_launch(void* const* d_in, const int* in_sizes, int n_in,
                              void* d_out, int out_size)
{
    const float* x  = (const float*)d_in[0];
    const float* wq = (const float*)d_in[1];
    const float* wk = (const float*)d_in[2];
    const float* wv = (const float*)d_in[3];
    float* out = (float*)d_out;

    const int smem_bytes = (TM * PS + TM * VS) * sizeof(float);  // 104448
    cudaFuncSetAttribute(attn_tc, cudaFuncAttributeMaxDynamicSharedMemorySize,
                         smem_bytes);

    qkv_tc<<<dim3((BB * TT) / TM, 3), 256>>>(x, wq, wk, wv);
    attn_tc<<<dim3(TT / TM, BB), 256, smem_bytes>>>(out);
}

// round 4
// speedup vs baseline: 4.0038x; 1.1420x over previous
#include <cuda_runtime.h>
#include <math.h>
#include <stdint.h>

#define BB 4
#define TT 4096
#define DD 1024
#define HD 64

#define TM 128   // q rows per attention block
#define TN 128   // keys per tile
#define PS 132   // P smem stride
#define KS 68    // K smem stride
#define VS 72    // V smem stride
#define XS 36    // projection smem stride (32 data + 4 pad)

// Scratch: projected Q (pre-scaled, tf32 bits), K, V (tf32 bits), weights (tf32).
__device__ float g_Q[BB * TT * HD];
__device__ float g_K[BB * TT * HD];
__device__ float g_V[BB * TT * HD];
__device__ float g_W[3 * HD * DD];

__device__ __forceinline__ uint32_t f2tf32(float x) {
    uint32_t r;
    asm("cvt.rna.tf32.f32 %0, %1;" : "=r"(r) : "f"(x));
    return r;
}
__device__ __forceinline__ float tf(float x) { return __uint_as_float(f2tf32(x)); }

__device__ __forceinline__ void cpa16(uint32_t s, const float* g) {
    asm volatile("cp.async.cg.shared.global [%0], [%1], 16;" :: "r"(s), "l"(g));
}
__device__ __forceinline__ void cpa_commit() {
    asm volatile("cp.async.commit_group;");
}
template <int N>
__device__ __forceinline__ void cpa_wait() {
    asm volatile("cp.async.wait_group %0;" :: "n"(N));
}

__device__ __forceinline__ void mma_tf32(float d[4], uint32_t a0, uint32_t a1,
                                         uint32_t a2, uint32_t a3,
                                         uint32_t b0, uint32_t b1) {
    asm("mma.sync.aligned.m16n8k8.row.col.f32.tf32.tf32.f32 "
        "{%0,%1,%2,%3}, {%4,%5,%6,%7}, {%8,%9}, {%0,%1,%2,%3};"
        : "+f"(d[0]), "+f"(d[1]), "+f"(d[2]), "+f"(d[3])
        : "r"(a0), "r"(a1), "r"(a2), "r"(a3), "r"(b0), "r"(b1));
}

// ---------------------------------------------------------------------------
// Weight prep: concat wq|wk|wv into g_W, tf32-rounded. 192 rows x 1024.
// ---------------------------------------------------------------------------
__global__ void wprep(const float* __restrict__ wq, const float* __restrict__ wk,
                      const float* __restrict__ wv)
{
    int r = blockIdx.x;
    const float* src = (r < 64) ? (wq + r * DD)
                     : (r < 128) ? (wk + (r - 64) * DD)
                                 : (wv + (r - 128) * DD);
    float* dst = g_W + r * DD;
    for (int i = threadIdx.x; i < DD; i += blockDim.x) dst[i] = tf(src[i]);
}

// ---------------------------------------------------------------------------
// Fused QKV projection. Grid 128, block 256 (8 warps). Reads x once.
// Warp w: rows 16w..16w+15; all 192 output cols (24 n-blocks).
// 2-stage cp.async on x and weight tiles (BK=32).
// Epilogue: Q scaled by 0.125; all outputs tf32-rounded.
// ---------------------------------------------------------------------------
__global__ __launch_bounds__(256) void qkv_fused(const float* __restrict__ x)
{
    extern __shared__ float sm[];
    // xs stages: 2 x [128][36]; ws stages: 2 x [192][36]
    float* xs0 = sm;                  // 4608 floats each
    float* ws0 = sm + 2 * TM * XS;    // 6912 floats each

    const int tid  = threadIdx.x;
    const int w    = tid >> 5;
    const int lane = tid & 31;
    const int g    = lane >> 2;
    const int c    = lane & 3;
    const int m0   = blockIdx.x * TM;

    const int xrow = tid >> 3, xc4 = (tid & 7) << 2;  // x loads: 4 chunks/thread

    float o[24][4];
    #pragma unroll
    for (int ni = 0; ni < 24; ni++)
        #pragma unroll
        for (int j = 0; j < 4; j++) o[ni][j] = 0.0f;

    // prefetch k0 = 0 into stage 0
    {
        float* xs = xs0;
        float* ws = ws0;
        #pragma unroll
        for (int i = 0; i < 4; i++) {
            int row = xrow + i * 32;
            cpa16((uint32_t)__cvta_generic_to_shared(xs + row * XS + xc4),
                  x + (m0 + row) * DD + xc4);
        }
        #pragma unroll
        for (int i = 0; i < 6; i++) {
            int idx = tid + i * 256;
            int row = idx >> 3, c4 = (idx & 7) << 2;
            cpa16((uint32_t)__cvta_generic_to_shared(ws + row * XS + c4),
                  g_W + row * DD + c4);
        }
        cpa_commit();
    }

    for (int it = 0; it < DD / 32; it++) {
        const int cur = it & 1;
        if (it + 1 < DD / 32) {
            const int k0 = (it + 1) * 32;
            float* xs = xs0 + ((it + 1) & 1) * TM * XS;
            float* ws = ws0 + ((it + 1) & 1) * 192 * XS;
            #pragma unroll
            for (int i = 0; i < 4; i++) {
                int row = xrow + i * 32;
                cpa16((uint32_t)__cvta_generic_to_shared(xs + row * XS + xc4),
                      x + (m0 + row) * DD + k0 + xc4);
            }
            #pragma unroll
            for (int i = 0; i < 6; i++) {
                int idx = tid + i * 256;
                int row = idx >> 3, c4 = (idx & 7) << 2;
                cpa16((uint32_t)__cvta_generic_to_shared(ws + row * XS + c4),
                      g_W + row * DD + k0 + c4);
            }
            cpa_commit();
            cpa_wait<1>();
        } else {
            cpa_wait<0>();
        }
        __syncthreads();

        const float* xs = xs0 + cur * TM * XS;
        const float* ws = ws0 + cur * 192 * XS;
        #pragma unroll
        for (int kc = 0; kc < 4; kc++) {
            const float* ar = xs + (16 * w + g) * XS + 8 * kc + c;
            uint32_t a0 = f2tf32(ar[0]);
            uint32_t a1 = f2tf32(ar[8 * XS]);
            uint32_t a2 = f2tf32(ar[4]);
            uint32_t a3 = f2tf32(ar[8 * XS + 4]);
            const float* br = ws + g * XS + 8 * kc + c;
            #pragma unroll
            for (int ni = 0; ni < 24; ni++) {
                uint32_t b0 = __float_as_uint(br[8 * ni * XS]);
                uint32_t b1 = __float_as_uint(br[8 * ni * XS + 4]);
                mma_tf32(o[ni], a0, a1, a2, a3, b0, b1);
            }
        }
        __syncthreads();
    }

    #pragma unroll
    for (int ni = 0; ni < 24; ni++) {
        float* outp = (ni < 8) ? g_Q : (ni < 16) ? g_K : g_V;
        float s = (ni < 8) ? 0.125f : 1.0f;
        int col = 8 * (ni & 7) + 2 * c;
        float* ob = outp + (m0 + 16 * w) * HD;
        *(float2*)(ob + g * HD + col) =
            make_float2(tf(o[ni][0] * s), tf(o[ni][1] * s));
        *(float2*)(ob + (g + 8) * HD + col) =
            make_float2(tf(o[ni][2] * s), tf(o[ni][3] * s));
    }
}

// ---------------------------------------------------------------------------
// Flash attention, tf32, cp.async double-buffered K/V (already tf32 bits).
// Grid (32, 4) = 128 blocks, 256 threads. Warp w owns q rows 16w..16w+15.
// Smem: K 2x[128][68] + V 2x[128][72] + P [128][132] = 210944 B dynamic.
// ---------------------------------------------------------------------------
__global__ void __launch_bounds__(256) attn_tc(float* __restrict__ out)
{
    extern __shared__ float sm[];
    float* Kst0 = sm;                      // 2 x 8704 floats
    float* Vst0 = sm + 2 * TM * KS;        // 2 x 9216 floats
    float* Pbuf = sm + 2 * TM * KS + 2 * TM * VS;  // 16896 floats

    const int tid  = threadIdx.x;
    const int w    = tid >> 5;
    const int lane = tid & 31;
    const int g    = lane >> 2;
    const int c    = lane & 3;

    const int b  = blockIdx.y;
    const int t0 = blockIdx.x * TM;

    const int lrow = tid >> 1;            // KV loads: 8 chunks each
    const int lc4a = (tid & 1) << 3;      // two float4 per row half

    // Q fragments: already scaled & tf32-rounded in gmem
    uint32_t qa[8][4];
    {
        const float* qb = g_Q + (b * TT + t0 + 16 * w) * HD;
        #pragma unroll
        for (int ks = 0; ks < 8; ks++) {
            int col = 8 * ks + c;
            qa[ks][0] = __float_as_uint(qb[g * HD + col]);
            qa[ks][1] = __float_as_uint(qb[(g + 8) * HD + col]);
            qa[ks][2] = __float_as_uint(qb[g * HD + col + 4]);
            qa[ks][3] = __float_as_uint(qb[(g + 8) * HD + col + 4]);
        }
    }

    float m0r = -INFINITY, m1r = -INFINITY, l0 = 0.0f, l1 = 0.0f;
    float o[8][4];
    #pragma unroll
    for (int ni = 0; ni < 8; ni++)
        #pragma unroll
        for (int j = 0; j < 4; j++) o[ni][j] = 0.0f;

    const float* kg0 = g_K + b * TT * HD;
    const float* vg0 = g_V + b * TT * HD;

    // prefetch tile 0 into stage 0
    {
        #pragma unroll
        for (int i = 0; i < 8; i++) {
            int idx = tid + i * 256;
            int row = idx >> 4, c4 = (idx & 15) << 2;
            cpa16((uint32_t)__cvta_generic_to_shared(Kst0 + row * KS + c4),
                  kg0 + row * HD + c4);
            cpa16((uint32_t)__cvta_generic_to_shared(Vst0 + row * VS + c4),
                  vg0 + row * HD + c4);
        }
        cpa_commit();
    }

    for (int it = 0; it < TT / TN; it++) {
        const int cur = it & 1;
        if (it + 1 < TT / TN) {
            const float* kg = kg0 + (it + 1) * TN * HD;
            const float* vg = vg0 + (it + 1) * TN * HD;
            float* Kn = Kst0 + ((it + 1) & 1) * TM * KS;
            float* Vn = Vst0 + ((it + 1) & 1) * TM * VS;
            #pragma unroll
            for (int i = 0; i < 8; i++) {
                int idx = tid + i * 256;
                int row = idx >> 4, c4 = (idx & 15) << 2;
                cpa16((uint32_t)__cvta_generic_to_shared(Kn + row * KS + c4),
                      kg + row * HD + c4);
                cpa16((uint32_t)__cvta_generic_to_shared(Vn + row * VS + c4),
                      vg + row * HD + c4);
            }
            cpa_commit();
            cpa_wait<1>();
        } else {
            cpa_wait<0>();
        }
        __syncthreads();

        const float* Kbuf = Kst0 + cur * TM * KS;
        const float* Vbuf = Vst0 + cur * TM * VS;

        // S = Q @ K^T : per warp 16 x 128
        float s_[16][4];
        #pragma unroll
        for (int ni = 0; ni < 16; ni++) {
            s_[ni][0] = s_[ni][1] = s_[ni][2] = s_[ni][3] = 0.0f;
            const float* kr = Kbuf + (8 * ni + g) * KS + c;
            #pragma unroll
            for (int ks = 0; ks < 8; ks++) {
                uint32_t b0 = __float_as_uint(kr[8 * ks]);
                uint32_t b1 = __float_as_uint(kr[8 * ks + 4]);
                mma_tf32(s_[ni], qa[ks][0], qa[ks][1], qa[ks][2], qa[ks][3], b0, b1);
            }
        }

        // online softmax (rows g, g+8; quad shfl reductions)
        float rx0 = -INFINITY, rx1 = -INFINITY;
        #pragma unroll
        for (int ni = 0; ni < 16; ni++) {
            rx0 = fmaxf(rx0, fmaxf(s_[ni][0], s_[ni][1]));
            rx1 = fmaxf(rx1, fmaxf(s_[ni][2], s_[ni][3]));
        }
        rx0 = fmaxf(rx0, __shfl_xor_sync(0xffffffffu, rx0, 1));
        rx0 = fmaxf(rx0, __shfl_xor_sync(0xffffffffu, rx0, 2));
        rx1 = fmaxf(rx1, __shfl_xor_sync(0xffffffffu, rx1, 1));
        rx1 = fmaxf(rx1, __shfl_xor_sync(0xffffffffu, rx1, 2));
        float mn0 = fmaxf(m0r, rx0), mn1 = fmaxf(m1r, rx1);
        float al0 = __expf(m0r - mn0), al1 = __expf(m1r - mn1);
        m0r = mn0; m1r = mn1;
        float rs0 = 0.0f, rs1 = 0.0f;
        #pragma unroll
        for (int ni = 0; ni < 16; ni++) {
            s_[ni][0] = __expf(s_[ni][0] - mn0);
            s_[ni][1] = __expf(s_[ni][1] - mn0);
            s_[ni][2] = __expf(s_[ni][2] - mn1);
            s_[ni][3] = __expf(s_[ni][3] - mn1);
            rs0 += s_[ni][0] + s_[ni][1];
            rs1 += s_[ni][2] + s_[ni][3];
        }
        rs0 += __shfl_xor_sync(0xffffffffu, rs0, 1);
        rs0 += __shfl_xor_sync(0xffffffffu, rs0, 2);
        rs1 += __shfl_xor_sync(0xffffffffu, rs1, 1);
        rs1 += __shfl_xor_sync(0xffffffffu, rs1, 2);
        l0 = l0 * al0 + rs0;
        l1 = l1 * al1 + rs1;
        #pragma unroll
        for (int ni = 0; ni < 8; ni++) {
            o[ni][0] *= al0; o[ni][1] *= al0;
            o[ni][2] *= al1; o[ni][3] *= al1;
        }

        // P -> smem (own rows only; warp-local)
        float* pr0 = Pbuf + (16 * w + g) * PS + 2 * c;
        float* pr1 = pr0 + 8 * PS;
        #pragma unroll
        for (int ni = 0; ni < 16; ni++) {
            *(float2*)(pr0 + 8 * ni) = make_float2(tf(s_[ni][0]), tf(s_[ni][1]));
            *(float2*)(pr1 + 8 * ni) = make_float2(tf(s_[ni][2]), tf(s_[ni][3]));
        }
        __syncwarp();

        // O += P @ V
        #pragma unroll
        for (int ki = 0; ki < 16; ki++) {
            const float* pa = Pbuf + (16 * w + g) * PS + 8 * ki + c;
            uint32_t a0 = __float_as_uint(pa[0]);
            uint32_t a1 = __float_as_uint(pa[8 * PS]);
            uint32_t a2 = __float_as_uint(pa[4]);
            uint32_t a3 = __float_as_uint(pa[8 * PS + 4]);
            const float* vr = Vbuf + (8 * ki + c) * VS + g;
            #pragma unroll
            for (int ni = 0; ni < 8; ni++) {
                uint32_t b0 = __float_as_uint(vr[8 * ni]);
                uint32_t b1 = __float_as_uint(vr[8 * ni + 4 * VS]);
                mma_tf32(o[ni], a0, a1, a2, a3, b0, b1);
            }
        }
        __syncthreads();  // stage `cur` fully consumed before next prefetch
    }

    float inv0 = 1.0f / l0, inv1 = 1.0f / l1;
    float* ob = out + (b * TT + t0 + 16 * w) * HD;
    #pragma unroll
    for (int ni = 0; ni < 8; ni++) {
        int col = 8 * ni + 2 * c;
        *(float2*)(ob + g * HD + col) =
            make_float2(o[ni][0] * inv0, o[ni][1] * inv0);
        *(float2*)(ob + (g + 8) * HD + col) =
            make_float2(o[ni][2] * inv1, o[ni][3] * inv1);
    }
}

extern "C" void kernel_launch(void* const* d_in, const int* in_sizes, int n_in,
                              void* d_out, int out_size)
{
    const float* x  = (const float*)d_in[0];
    const float* wq = (const float*)d_in[1];
    const float* wk = (const float*)d_in[2];
    const float* wv = (const float*)d_in[3];
    float* out = (float*)d_out;

    const int qkv_smem  = (2 * TM * XS + 2 * 192 * XS) * sizeof(float);   // 92160
    const int attn_smem = (2 * TM * KS + 2 * TM * VS + TM * PS) * sizeof(float); // 210944
    cudaFuncSetAttribute(qkv_fused, cudaFuncAttributeMaxDynamicSharedMemorySize,
                         qkv_smem);
    cudaFuncSetAttribute(attn_tc, cudaFuncAttributeMaxDynamicSharedMemorySize,
                         attn_smem);

    wprep<<<192, 256>>>(wq, wk, wv);
    qkv_fused<<<(BB * TT) / TM, 256, qkv_smem>>>(x);
    attn_tc<<<dim3(TT / TM, BB), 256, attn_smem>>>(out);
}

// round 5
// speedup vs baseline: 4.0621x; 1.0146x over previous
#include <cuda_runtime.h>
#include <math.h>
#include <stdint.h>

#define BB 4
#define TT 4096
#define DD 1024
#define HD 64

#define TM 128   // q rows per attention block
#define TN 128   // keys per tile (64 per warp of a pair)
#define PS2 68   // per-warp P smem stride
#define KS 68    // K smem stride
#define VS 72    // V smem stride
#define XS 36    // projection smem stride

__device__ float g_Q[BB * TT * HD];
__device__ float g_K[BB * TT * HD];
__device__ float g_V[BB * TT * HD];
__device__ float g_W[3 * HD * DD];

__device__ __forceinline__ uint32_t f2tf32(float x) {
    uint32_t r;
    asm("cvt.rna.tf32.f32 %0, %1;" : "=r"(r) : "f"(x));
    return r;
}
__device__ __forceinline__ float tf(float x) { return __uint_as_float(f2tf32(x)); }

__device__ __forceinline__ void cpa16(uint32_t s, const float* g) {
    asm volatile("cp.async.cg.shared.global [%0], [%1], 16;" :: "r"(s), "l"(g));
}
__device__ __forceinline__ void cpa_commit() {
    asm volatile("cp.async.commit_group;");
}
template <int N>
__device__ __forceinline__ void cpa_wait() {
    asm volatile("cp.async.wait_group %0;" :: "n"(N));
}

__device__ __forceinline__ void mma_tf32(float d[4], uint32_t a0, uint32_t a1,
                                         uint32_t a2, uint32_t a3,
                                         uint32_t b0, uint32_t b1) {
    asm("mma.sync.aligned.m16n8k8.row.col.f32.tf32.tf32.f32 "
        "{%0,%1,%2,%3}, {%4,%5,%6,%7}, {%8,%9}, {%0,%1,%2,%3};"
        : "+f"(d[0]), "+f"(d[1]), "+f"(d[2]), "+f"(d[3])
        : "r"(a0), "r"(a1), "r"(a2), "r"(a3), "r"(b0), "r"(b1));
}

// ---------------------------------------------------------------------------
// Weight prep (unchanged): concat wq|wk|wv into g_W, tf32-rounded.
// ---------------------------------------------------------------------------
__global__ void wprep(const float* __restrict__ wq, const float* __restrict__ wk,
                      const float* __restrict__ wv)
{
    int r = blockIdx.x;
    const float* src = (r < 64) ? (wq + r * DD)
                     : (r < 128) ? (wk + (r - 64) * DD)
                                 : (wv + (r - 128) * DD);
    float* dst = g_W + r * DD;
    for (int i = threadIdx.x; i < DD; i += blockDim.x) dst[i] = tf(src[i]);
}

// ---------------------------------------------------------------------------
// Fused QKV projection (unchanged from R4).
// ---------------------------------------------------------------------------
__global__ __launch_bounds__(256) void qkv_fused(const float* __restrict__ x)
{
    extern __shared__ float sm[];
    float* xs0 = sm;
    float* ws0 = sm + 2 * TM * XS;

    const int tid  = threadIdx.x;
    const int w    = tid >> 5;
    const int lane = tid & 31;
    const int g    = lane >> 2;
    const int c    = lane & 3;
    const int m0   = blockIdx.x * TM;

    const int xrow = tid >> 3, xc4 = (tid & 7) << 2;

    float o[24][4];
    #pragma unroll
    for (int ni = 0; ni < 24; ni++)
        #pragma unroll
        for (int j = 0; j < 4; j++) o[ni][j] = 0.0f;

    {
        float* xs = xs0;
        float* ws = ws0;
        #pragma unroll
        for (int i = 0; i < 4; i++) {
            int row = xrow + i * 32;
            cpa16((uint32_t)__cvta_generic_to_shared(xs + row * XS + xc4),
                  x + (m0 + row) * DD + xc4);
        }
        #pragma unroll
        for (int i = 0; i < 6; i++) {
            int idx = tid + i * 256;
            int row = idx >> 3, c4 = (idx & 7) << 2;
            cpa16((uint32_t)__cvta_generic_to_shared(ws + row * XS + c4),
                  g_W + row * DD + c4);
        }
        cpa_commit();
    }

    for (int it = 0; it < DD / 32; it++) {
        const int cur = it & 1;
        if (it + 1 < DD / 32) {
            const int k0 = (it + 1) * 32;
            float* xs = xs0 + ((it + 1) & 1) * TM * XS;
            float* ws = ws0 + ((it + 1) & 1) * 192 * XS;
            #pragma unroll
            for (int i = 0; i < 4; i++) {
                int row = xrow + i * 32;
                cpa16((uint32_t)__cvta_generic_to_shared(xs + row * XS + xc4),
                      x + (m0 + row) * DD + k0 + xc4);
            }
            #pragma unroll
            for (int i = 0; i < 6; i++) {
                int idx = tid + i * 256;
                int row = idx >> 3, c4 = (idx & 7) << 2;
                cpa16((uint32_t)__cvta_generic_to_shared(ws + row * XS + c4),
                      g_W + row * DD + k0 + c4);
            }
            cpa_commit();
            cpa_wait<1>();
        } else {
            cpa_wait<0>();
        }
        __syncthreads();

        const float* xs = xs0 + cur * TM * XS;
        const float* ws = ws0 + cur * 192 * XS;
        #pragma unroll
        for (int kc = 0; kc < 4; kc++) {
            const float* ar = xs + (16 * w + g) * XS + 8 * kc + c;
            uint32_t a0 = f2tf32(ar[0]);
            uint32_t a1 = f2tf32(ar[8 * XS]);
            uint32_t a2 = f2tf32(ar[4]);
            uint32_t a3 = f2tf32(ar[8 * XS + 4]);
            const float* br = ws + g * XS + 8 * kc + c;
            #pragma unroll
            for (int ni = 0; ni < 24; ni++) {
                uint32_t b0 = __float_as_uint(br[8 * ni * XS]);
                uint32_t b1 = __float_as_uint(br[8 * ni * XS + 4]);
                mma_tf32(o[ni], a0, a1, a2, a3, b0, b1);
            }
        }
        __syncthreads();
    }

    #pragma unroll
    for (int ni = 0; ni < 24; ni++) {
        float* outp = (ni < 8) ? g_Q : (ni < 16) ? g_K : g_V;
        float s = (ni < 8) ? 0.125f : 1.0f;
        int col = 8 * (ni & 7) + 2 * c;
        float* ob = outp + (m0 + 16 * w) * HD;
        *(float2*)(ob + g * HD + col) =
            make_float2(tf(o[ni][0] * s), tf(o[ni][1] * s));
        *(float2*)(ob + (g + 8) * HD + col) =
            make_float2(tf(o[ni][2] * s), tf(o[ni][3] * s));
    }
}

// ---------------------------------------------------------------------------
// Flash attention, split-N, 512 threads (16 warps).
// Warp pair (wr = w>>1, kh = w&1): both own q rows 16*wr..+15; warp kh
// handles keys [64*kh, 64*kh+64) of every tile -> half of all keys.
// Independent online softmax per warp; final in-smem pair combine.
// Smem: K 2x[128][68] + V 2x[128][72] + P 16x[16][68] = 212992 B.
// ---------------------------------------------------------------------------
__global__ void __launch_bounds__(512, 1) attn_tc(float* __restrict__ out)
{
    extern __shared__ float sm[];
    float* Kst0 = sm;                              // 2 x 8704 floats
    float* Vst0 = sm + 2 * TM * KS;                // 2 x 9216 floats
    float* Pbuf = sm + 2 * TM * KS + 2 * TM * VS;  // 16 x 16 x 68

    const int tid  = threadIdx.x;
    const int w    = tid >> 5;
    const int wr   = w >> 1;
    const int kh   = w & 1;
    const int lane = tid & 31;
    const int g    = lane >> 2;
    const int c    = lane & 3;

    const int b  = blockIdx.y;
    const int t0 = blockIdx.x * TM;

    // Q fragments (rows 16*wr..): pre-scaled, tf32 bits in gmem
    uint32_t qa[8][4];
    {
        const float* qb = g_Q + (b * TT + t0 + 16 * wr) * HD;
        #pragma unroll
        for (int ks = 0; ks < 8; ks++) {
            int col = 8 * ks + c;
            qa[ks][0] = __float_as_uint(qb[g * HD + col]);
            qa[ks][1] = __float_as_uint(qb[(g + 8) * HD + col]);
            qa[ks][2] = __float_as_uint(qb[g * HD + col + 4]);
            qa[ks][3] = __float_as_uint(qb[(g + 8) * HD + col + 4]);
        }
    }

    float m0r = -INFINITY, m1r = -INFINITY, l0 = 0.0f, l1 = 0.0f;
    float o[8][4];
    #pragma unroll
    for (int ni = 0; ni < 8; ni++)
        #pragma unroll
        for (int j = 0; j < 4; j++) o[ni][j] = 0.0f;

    const float* kg0 = g_K + b * TT * HD;
    const float* vg0 = g_V + b * TT * HD;

    // prefetch tile 0
    {
        #pragma unroll
        for (int i = 0; i < 4; i++) {
            int idx = tid + i * 512;
            int row = idx >> 4, c4 = (idx & 15) << 2;
            cpa16((uint32_t)__cvta_generic_to_shared(Kst0 + row * KS + c4),
                  kg0 + row * HD + c4);
            cpa16((uint32_t)__cvta_generic_to_shared(Vst0 + row * VS + c4),
                  vg0 + row * HD + c4);
        }
        cpa_commit();
    }

    float* Pw = Pbuf + w * 16 * PS2;

    for (int it = 0; it < TT / TN; it++) {
        const int cur = it & 1;
        if (it + 1 < TT / TN) {
            const float* kg = kg0 + (it + 1) * TN * HD;
            const float* vg = vg0 + (it + 1) * TN * HD;
            float* Kn = Kst0 + ((it + 1) & 1) * TM * KS;
            float* Vn = Vst0 + ((it + 1) & 1) * TM * VS;
            #pragma unroll
            for (int i = 0; i < 4; i++) {
                int idx = tid + i * 512;
                int row = idx >> 4, c4 = (idx & 15) << 2;
                cpa16((uint32_t)__cvta_generic_to_shared(Kn + row * KS + c4),
                      kg + row * HD + c4);
                cpa16((uint32_t)__cvta_generic_to_shared(Vn + row * VS + c4),
                      vg + row * HD + c4);
            }
            cpa_commit();
            cpa_wait<1>();
        } else {
            cpa_wait<0>();
        }
        __syncthreads();

        const float* Kbuf = Kst0 + cur * TM * KS + 64 * kh * KS;
        const float* Vbuf = Vst0 + cur * TM * VS + 64 * kh * VS;

        // S = Q @ K^T : per warp 16 x 64 (its key half)
        float s_[8][4];
        #pragma unroll
        for (int ni = 0; ni < 8; ni++) {
            s_[ni][0] = s_[ni][1] = s_[ni][2] = s_[ni][3] = 0.0f;
            const float* kr = Kbuf + (8 * ni + g) * KS + c;
            #pragma unroll
            for (int ks = 0; ks < 8; ks++) {
                uint32_t b0 = __float_as_uint(kr[8 * ks]);
                uint32_t b1 = __float_as_uint(kr[8 * ks + 4]);
                mma_tf32(s_[ni], qa[ks][0], qa[ks][1], qa[ks][2], qa[ks][3], b0, b1);
            }
        }

        // online softmax over this warp's 64 keys
        float rx0 = -INFINITY, rx1 = -INFINITY;
        #pragma unroll
        for (int ni = 0; ni < 8; ni++) {
            rx0 = fmaxf(rx0, fmaxf(s_[ni][0], s_[ni][1]));
            rx1 = fmaxf(rx1, fmaxf(s_[ni][2], s_[ni][3]));
        }
        rx0 = fmaxf(rx0, __shfl_xor_sync(0xffffffffu, rx0, 1));
        rx0 = fmaxf(rx0, __shfl_xor_sync(0xffffffffu, rx0, 2));
        rx1 = fmaxf(rx1, __shfl_xor_sync(0xffffffffu, rx1, 1));
        rx1 = fmaxf(rx1, __shfl_xor_sync(0xffffffffu, rx1, 2));
        float mn0 = fmaxf(m0r, rx0), mn1 = fmaxf(m1r, rx1);
        float al0 = __expf(m0r - mn0), al1 = __expf(m1r - mn1);
        m0r = mn0; m1r = mn1;
        float rs0 = 0.0f, rs1 = 0.0f;
        #pragma unroll
        for (int ni = 0; ni < 8; ni++) {
            s_[ni][0] = __expf(s_[ni][0] - mn0);
            s_[ni][1] = __expf(s_[ni][1] - mn0);
            s_[ni][2] = __expf(s_[ni][2] - mn1);
            s_[ni][3] = __expf(s_[ni][3] - mn1);
            rs0 += s_[ni][0] + s_[ni][1];
            rs1 += s_[ni][2] + s_[ni][3];
        }
        rs0 += __shfl_xor_sync(0xffffffffu, rs0, 1);
        rs0 += __shfl_xor_sync(0xffffffffu, rs0, 2);
        rs1 += __shfl_xor_sync(0xffffffffu, rs1, 1);
        rs1 += __shfl_xor_sync(0xffffffffu, rs1, 2);
        l0 = l0 * al0 + rs0;
        l1 = l1 * al1 + rs1;
        #pragma unroll
        for (int ni = 0; ni < 8; ni++) {
            o[ni][0] *= al0; o[ni][1] *= al0;
            o[ni][2] *= al1; o[ni][3] *= al1;
        }

        // P -> per-warp smem region
        float* pr0 = Pw + g * PS2 + 2 * c;
        float* pr1 = pr0 + 8 * PS2;
        #pragma unroll
        for (int ni = 0; ni < 8; ni++) {
            *(float2*)(pr0 + 8 * ni) = make_float2(tf(s_[ni][0]), tf(s_[ni][1]));
            *(float2*)(pr1 + 8 * ni) = make_float2(tf(s_[ni][2]), tf(s_[ni][3]));
        }
        __syncwarp();

        // O += P @ V (k-dim = 64 keys of this half)
        #pragma unroll
        for (int ki = 0; ki < 8; ki++) {
            const float* pa = Pw + g * PS2 + 8 * ki + c;
            uint32_t a0 = __float_as_uint(pa[0]);
            uint32_t a1 = __float_as_uint(pa[8 * PS2]);
            uint32_t a2 = __float_as_uint(pa[4]);
            uint32_t a3 = __float_as_uint(pa[8 * PS2 + 4]);
            const float* vr = Vbuf + (8 * ki + c) * VS + g;
            #pragma unroll
            for (int ni = 0; ni < 8; ni++) {
                uint32_t b0 = __float_as_uint(vr[8 * ni]);
                uint32_t b1 = __float_as_uint(vr[8 * ni + 4 * VS]);
                mma_tf32(o[ni], a0, a1, a2, a3, b0, b1);
            }
        }
        __syncthreads();  // stage fully consumed before next prefetch reuses it
    }

    // ---- pair combine: kh=1 publishes (O, m, l); kh=0 merges + writes out ----
    float* Ob = Kst0;                 // 128 x 68 region (reuse K stage area)
    float* Ml = Kst0 + TM * KS;       // 128 x 2 (fits in V area offsetwise; K big)

    const int row0 = 16 * wr + g;
    const int row1 = row0 + 8;
    if (kh == 1) {
        #pragma unroll
        for (int ni = 0; ni < 8; ni++) {
            int col = 8 * ni + 2 * c;
            *(float2*)(Ob + row0 * 68 + col) = make_float2(o[ni][0], o[ni][1]);
            *(float2*)(Ob + row1 * 68 + col) = make_float2(o[ni][2], o[ni][3]);
        }
        if (c == 0) {
            Ml[row0 * 2 + 0] = m0r; Ml[row0 * 2 + 1] = l0;
            Ml[row1 * 2 + 0] = m1r; Ml[row1 * 2 + 1] = l1;
        }
    }
    __syncthreads();

    if (kh == 0) {
        float pm0 = Ml[row0 * 2 + 0], pl0 = Ml[row0 * 2 + 1];
        float pm1 = Ml[row1 * 2 + 0], pl1 = Ml[row1 * 2 + 1];
        float M0 = fmaxf(m0r, pm0), M1 = fmaxf(m1r, pm1);
        float e0 = __expf(m0r - M0), p0 = __expf(pm0 - M0);
        float e1 = __expf(m1r - M1), p1 = __expf(pm1 - M1);
        float inv0 = 1.0f / (l0 * e0 + pl0 * p0);
        float inv1 = 1.0f / (l1 * e1 + pl1 * p1);

        float* ob = out + (b * TT + t0) * HD;
        #pragma unroll
        for (int ni = 0; ni < 8; ni++) {
            int col = 8 * ni + 2 * c;
            float2 q0 = *(const float2*)(Ob + row0 * 68 + col);
            float2 q1 = *(const float2*)(Ob + row1 * 68 + col);
            *(float2*)(ob + row0 * HD + col) =
                make_float2((o[ni][0] * e0 + q0.x * p0) * inv0,
                            (o[ni][1] * e0 + q0.y * p0) * inv0);
            *(float2*)(ob + row1 * HD + col) =
                make_float2((o[ni][2] * e1 + q1.x * p1) * inv1,
                            (o[ni][3] * e1 + q1.y * p1) * inv1);
        }
    }
}

extern "C" void kernel_launch(void* const* d_in, const int* in_sizes, int n_in,
                              void* d_out, int out_size)
{
    const float* x  = (const float*)d_in[0];
    const float* wq = (const float*)d_in[1];
    const float* wk = (const float*)d_in[2];
    const float* wv = (const float*)d_in[3];
    float* out = (float*)d_out;

    const int qkv_smem  = (2 * TM * XS + 2 * 192 * XS) * sizeof(float);
    const int attn_smem = (2 * TM * KS + 2 * TM * VS + 16 * 16 * PS2) * sizeof(float);
    cudaFuncSetAttribute(qkv_fused, cudaFuncAttributeMaxDynamicSharedMemorySize,
                         qkv_smem);
    cudaFuncSetAttribute(attn_tc, cudaFuncAttributeMaxDynamicSharedMemorySize,
                         attn_smem);

    wprep<<<192, 256>>>(wq, wk, wv);
    qkv_fused<<<(BB * TT) / TM, 256, qkv_smem>>>(x);
    attn_tc<<<dim3(TT / TM, BB), 512, attn_smem>>>(out);
}

// round 8
// speedup vs baseline: 4.5227x; 1.1134x over previous
#include <cuda_runtime.h>
#include <math.h>
#include <stdint.h>

#define BB 4
#define TT 4096
#define DD 1024
#define HD 64

#define TM 128   // q rows per attention CTA
#define TN 128   // keys per tile
#define KS 68    // K smem stride (floats)
#define VS 72    // V smem stride
#define PSW 72   // per-warp P stride
#define XS 36    // projection smem stride

// floats offsets in attn smem
#define KF 0
#define VF (2 * TM * KS)              // 17408
#define PF (VF + 2 * TM * VS)         // 35840
#define ATTN_SMEM ((PF + 8 * 32 * PSW) * 4)   // 217088 bytes

// log2(e) folded into Q scale: softmax done in base-2
#define QSCALE (0.125f * 1.4426950408889634f)

__device__ float g_Q[BB * TT * HD];
__device__ float g_K[BB * TT * HD];
__device__ float g_V[BB * TT * HD];
__device__ float g_W[3 * HD * DD];

__device__ __forceinline__ uint32_t f2tf32(float x) {
    uint32_t r;
    asm("cvt.rna.tf32.f32 %0, %1;" : "=r"(r) : "f"(x));
    return r;
}
__device__ __forceinline__ float tf(float x) { return __uint_as_float(f2tf32(x)); }
__device__ __forceinline__ float ex2(float x) {
    float r;
    asm("ex2.approx.f32 %0, %1;" : "=f"(r) : "f"(x));
    return r;
}

__device__ __forceinline__ void cpa16(uint32_t s, const float* g) {
    asm volatile("cp.async.cg.shared.global [%0], [%1], 16;" :: "r"(s), "l"(g));
}
__device__ __forceinline__ void cpa_commit() {
    asm volatile("cp.async.commit_group;");
}
template <int N>
__device__ __forceinline__ void cpa_wait() {
    asm volatile("cp.async.wait_group %0;" :: "n"(N));
}

__device__ __forceinline__ void mma_tf32(float d[4], uint32_t a0, uint32_t a1,
                                         uint32_t a2, uint32_t a3,
                                         uint32_t b0, uint32_t b1) {
    asm("mma.sync.aligned.m16n8k8.row.col.f32.tf32.tf32.f32 "
        "{%0,%1,%2,%3}, {%4,%5,%6,%7}, {%8,%9}, {%0,%1,%2,%3};"
        : "+f"(d[0]), "+f"(d[1]), "+f"(d[2]), "+f"(d[3])
        : "r"(a0), "r"(a1), "r"(a2), "r"(a3), "r"(b0), "r"(b1));
}

// ---------------------------------------------------------------------------
// Weight prep
// ---------------------------------------------------------------------------
__global__ void wprep(const float* __restrict__ wq, const float* __restrict__ wk,
                      const float* __restrict__ wv)
{
    int r = blockIdx.x;
    const float* src = (r < 64) ? (wq + r * DD)
                     : (r < 128) ? (wk + (r - 64) * DD)
                                 : (wv + (r - 128) * DD);
    float* dst = g_W + r * DD;
    for (int i = threadIdx.x; i < DD; i += blockDim.x) dst[i] = tf(src[i]);
}

// ---------------------------------------------------------------------------
// Fused QKV projection (R4 structure). Q pre-scaled by 0.125*log2(e).
// ---------------------------------------------------------------------------
__global__ __launch_bounds__(256) void qkv_fused(const float* __restrict__ x)
{
    extern __shared__ float sm[];
    float* xs0 = sm;
    float* ws0 = sm + 2 * TM * XS;

    const int tid  = threadIdx.x;
    const int w    = tid >> 5;
    const int lane = tid & 31;
    const int g    = lane >> 2;
    const int c    = lane & 3;
    const int m0   = blockIdx.x * TM;

    const int xrow = tid >> 3, xc4 = (tid & 7) << 2;

    float o[24][4];
    #pragma unroll
    for (int ni = 0; ni < 24; ni++)
        #pragma unroll
        for (int j = 0; j < 4; j++) o[ni][j] = 0.0f;

    {
        #pragma unroll
        for (int i = 0; i < 4; i++) {
            int row = xrow + i * 32;
            cpa16((uint32_t)__cvta_generic_to_shared(xs0 + row * XS + xc4),
                  x + (m0 + row) * DD + xc4);
        }
        #pragma unroll
        for (int i = 0; i < 6; i++) {
            int idx = tid + i * 256;
            int row = idx >> 3, c4 = (idx & 7) << 2;
            cpa16((uint32_t)__cvta_generic_to_shared(ws0 + row * XS + c4),
                  g_W + row * DD + c4);
        }
        cpa_commit();
    }

    for (int it = 0; it < DD / 32; it++) {
        const int cur = it & 1;
        if (it + 1 < DD / 32) {
            const int k0 = (it + 1) * 32;
            float* xs = xs0 + ((it + 1) & 1) * TM * XS;
            float* ws = ws0 + ((it + 1) & 1) * 192 * XS;
            #pragma unroll
            for (int i = 0; i < 4; i++) {
                int row = xrow + i * 32;
                cpa16((uint32_t)__cvta_generic_to_shared(xs + row * XS + xc4),
                      x + (m0 + row) * DD + k0 + xc4);
            }
            #pragma unroll
            for (int i = 0; i < 6; i++) {
                int idx = tid + i * 256;
                int row = idx >> 3, c4 = (idx & 7) << 2;
                cpa16((uint32_t)__cvta_generic_to_shared(ws + row * XS + c4),
                      g_W + row * DD + k0 + c4);
            }
            cpa_commit();
            cpa_wait<1>();
        } else {
            cpa_wait<0>();
        }
        __syncthreads();

        const float* xs = xs0 + cur * TM * XS;
        const float* ws = ws0 + cur * 192 * XS;
        #pragma unroll
        for (int kc = 0; kc < 4; kc++) {
            const float* ar = xs + (16 * w + g) * XS + 8 * kc + c;
            uint32_t a0 = f2tf32(ar[0]);
            uint32_t a1 = f2tf32(ar[8 * XS]);
            uint32_t a2 = f2tf32(ar[4]);
            uint32_t a3 = f2tf32(ar[8 * XS + 4]);
            const float* br = ws + g * XS + 8 * kc + c;
            #pragma unroll
            for (int ni = 0; ni < 24; ni++) {
                uint32_t b0 = __float_as_uint(br[8 * ni * XS]);
                uint32_t b1 = __float_as_uint(br[8 * ni * XS + 4]);
                mma_tf32(o[ni], a0, a1, a2, a3, b0, b1);
            }
        }
        __syncthreads();
    }

    #pragma unroll
    for (int ni = 0; ni < 24; ni++) {
        float* outp = (ni < 8) ? g_Q : (ni < 16) ? g_K : g_V;
        float s = (ni < 8) ? QSCALE : 1.0f;
        int col = 8 * (ni & 7) + 2 * c;
        float* ob = outp + (m0 + 16 * w) * HD;
        *(float2*)(ob + g * HD + col) =
            make_float2(tf(o[ni][0] * s), tf(o[ni][1] * s));
        *(float2*)(ob + (g + 8) * HD + col) =
            make_float2(tf(o[ni][2] * s), tf(o[ni][3] * s));
    }
}

// ---------------------------------------------------------------------------
// Flash attention: 256 threads (8 warps). Warp = (wr = w>>1, kh = w&1).
// Warp owns 32 q rows (two 16-row chunks, Q frags in registers) and the
// kh-th 64-key half of every 128-key tile. B fragments (K, V) are loaded
// once per warp and reused across both A chunks -> 0.6x smem traffic.
// Softmax in base-2 (Q pre-scaled by log2e/8), no cross-warp comm until
// a single final pair-combine.
// ---------------------------------------------------------------------------
__global__ void __launch_bounds__(256, 1) attn_tc(float* __restrict__ out)
{
    extern __shared__ float sm[];
    float* Kst0 = sm + KF;
    float* Vst0 = sm + VF;
    float* Pw   = sm + PF + (threadIdx.x >> 5) * 32 * PSW;

    const int tid  = threadIdx.x;
    const int w    = tid >> 5;
    const int wr   = w >> 1;
    const int kh   = w & 1;
    const int lane = tid & 31;
    const int g    = lane >> 2;
    const int c    = lane & 3;

    const int b  = blockIdx.y;
    const int t0 = blockIdx.x * TM;

    // Q fragments for 2 chunks (rows 32wr+16ch+g, +8): one-time gmem reads
    uint32_t qa[2][8][4];
    {
        const float* qb = g_Q + (b * TT + t0 + 32 * wr) * HD;
        #pragma unroll
        for (int ch = 0; ch < 2; ch++) {
            const float* qc = qb + 16 * ch * HD;
            #pragma unroll
            for (int ks = 0; ks < 8; ks++) {
                int col = 8 * ks + c;
                qa[ch][ks][0] = __float_as_uint(qc[g * HD + col]);
                qa[ch][ks][1] = __float_as_uint(qc[(g + 8) * HD + col]);
                qa[ch][ks][2] = __float_as_uint(qc[g * HD + col + 4]);
                qa[ch][ks][3] = __float_as_uint(qc[(g + 8) * HD + col + 4]);
            }
        }
    }

    float m_[2][2], l_[2][2];
    #pragma unroll
    for (int ch = 0; ch < 2; ch++) {
        m_[ch][0] = m_[ch][1] = -INFINITY;
        l_[ch][0] = l_[ch][1] = 0.0f;
    }
    float o[2][8][4];
    #pragma unroll
    for (int ch = 0; ch < 2; ch++)
        #pragma unroll
        for (int ni = 0; ni < 8; ni++)
            #pragma unroll
            for (int j = 0; j < 4; j++) o[ch][ni][j] = 0.0f;

    const float* kg0 = g_K + b * TT * HD;
    const float* vg0 = g_V + b * TT * HD;

    // prefetch tile 0
    {
        #pragma unroll
        for (int i = 0; i < 8; i++) {
            int idx = tid + i * 256;
            int row = idx >> 4, c4 = (idx & 15) << 2;
            cpa16((uint32_t)__cvta_generic_to_shared(Kst0 + row * KS + c4),
                  kg0 + row * HD + c4);
            cpa16((uint32_t)__cvta_generic_to_shared(Vst0 + row * VS + c4),
                  vg0 + row * HD + c4);
        }
        cpa_commit();
    }

    for (int it = 0; it < TT / TN; it++) {
        const int cur = it & 1;
        if (it + 1 < TT / TN) {
            const float* kg = kg0 + (it + 1) * TN * HD;
            const float* vg = vg0 + (it + 1) * TN * HD;
            float* Kn = Kst0 + ((it + 1) & 1) * TM * KS;
            float* Vn = Vst0 + ((it + 1) & 1) * TM * VS;
            #pragma unroll
            for (int i = 0; i < 8; i++) {
                int idx = tid + i * 256;
                int row = idx >> 4, c4 = (idx & 15) << 2;
                cpa16((uint32_t)__cvta_generic_to_shared(Kn + row * KS + c4),
                      kg + row * HD + c4);
                cpa16((uint32_t)__cvta_generic_to_shared(Vn + row * VS + c4),
                      vg + row * HD + c4);
            }
            cpa_commit();
            cpa_wait<1>();
        } else {
            cpa_wait<0>();
        }
        __syncthreads();

        const float* Kbuf = Kst0 + cur * TM * KS + 64 * kh * KS;
        const float* Vbuf = Vst0 + cur * TM * VS + 64 * kh * VS;

        // ---- S = Q @ K^T : 32 rows x 64 keys; B frags shared by chunks ----
        float s_[2][8][4];
        #pragma unroll
        for (int ch = 0; ch < 2; ch++)
            #pragma unroll
            for (int ni = 0; ni < 8; ni++)
                #pragma unroll
                for (int j = 0; j < 4; j++) s_[ch][ni][j] = 0.0f;

        #pragma unroll
        for (int ni = 0; ni < 8; ni++) {
            const float* kr = Kbuf + (8 * ni + g) * KS + c;
            #pragma unroll
            for (int ks = 0; ks < 8; ks++) {
                uint32_t b0 = __float_as_uint(kr[8 * ks]);
                uint32_t b1 = __float_as_uint(kr[8 * ks + 4]);
                mma_tf32(s_[0][ni], qa[0][ks][0], qa[0][ks][1],
                         qa[0][ks][2], qa[0][ks][3], b0, b1);
                mma_tf32(s_[1][ni], qa[1][ks][0], qa[1][ks][1],
                         qa[1][ks][2], qa[1][ks][3], b0, b1);
            }
        }

        // ---- online softmax per chunk (base-2), write P ----
        #pragma unroll
        for (int ch = 0; ch < 2; ch++) {
            float rx0 = -INFINITY, rx1 = -INFINITY;
            #pragma unroll
            for (int ni = 0; ni < 8; ni++) {
                rx0 = fmaxf(rx0, fmaxf(s_[ch][ni][0], s_[ch][ni][1]));
                rx1 = fmaxf(rx1, fmaxf(s_[ch][ni][2], s_[ch][ni][3]));
            }
            rx0 = fmaxf(rx0, __shfl_xor_sync(0xffffffffu, rx0, 1));
            rx0 = fmaxf(rx0, __shfl_xor_sync(0xffffffffu, rx0, 2));
            rx1 = fmaxf(rx1, __shfl_xor_sync(0xffffffffu, rx1, 1));
            rx1 = fmaxf(rx1, __shfl_xor_sync(0xffffffffu, rx1, 2));
            float mn0 = fmaxf(m_[ch][0], rx0), mn1 = fmaxf(m_[ch][1], rx1);
            float al0 = ex2(m_[ch][0] - mn0), al1 = ex2(m_[ch][1] - mn1);
            m_[ch][0] = mn0; m_[ch][1] = mn1;
            float rs0 = 0.0f, rs1 = 0.0f;
            float* pr0 = Pw + (16 * ch + g) * PSW + 2 * c;
            float* pr1 = pr0 + 8 * PSW;
            #pragma unroll
            for (int ni = 0; ni < 8; ni++) {
                float e0 = ex2(s_[ch][ni][0] - mn0);
                float e1 = ex2(s_[ch][ni][1] - mn0);
                float e2 = ex2(s_[ch][ni][2] - mn1);
                float e3 = ex2(s_[ch][ni][3] - mn1);
                rs0 += e0 + e1;
                rs1 += e2 + e3;
                *(float2*)(pr0 + 8 * ni) = make_float2(tf(e0), tf(e1));
                *(float2*)(pr1 + 8 * ni) = make_float2(tf(e2), tf(e3));
            }
            rs0 += __shfl_xor_sync(0xffffffffu, rs0, 1);
            rs0 += __shfl_xor_sync(0xffffffffu, rs0, 2);
            rs1 += __shfl_xor_sync(0xffffffffu, rs1, 1);
            rs1 += __shfl_xor_sync(0xffffffffu, rs1, 2);
            l_[ch][0] = l_[ch][0] * al0 + rs0;
            l_[ch][1] = l_[ch][1] * al1 + rs1;
            #pragma unroll
            for (int ni = 0; ni < 8; ni++) {
                o[ch][ni][0] *= al0; o[ch][ni][1] *= al0;
                o[ch][ni][2] *= al1; o[ch][ni][3] *= al1;
            }
        }
        __syncwarp();

        // ---- O += P @ V : B frags shared by chunks ----
        #pragma unroll
        for (int ki = 0; ki < 8; ki++) {
            const float* pa0 = Pw + g * PSW + 8 * ki + c;
            const float* pa1 = pa0 + 16 * PSW;
            uint32_t a00 = __float_as_uint(pa0[0]);
            uint32_t a01 = __float_as_uint(pa0[8 * PSW]);
            uint32_t a02 = __float_as_uint(pa0[4]);
            uint32_t a03 = __float_as_uint(pa0[8 * PSW + 4]);
            uint32_t a10 = __float_as_uint(pa1[0]);
            uint32_t a11 = __float_as_uint(pa1[8 * PSW]);
            uint32_t a12 = __float_as_uint(pa1[4]);
            uint32_t a13 = __float_as_uint(pa1[8 * PSW + 4]);
            const float* vr = Vbuf + (8 * ki + c) * VS + g;
            #pragma unroll
            for (int ni = 0; ni < 8; ni++) {
                uint32_t b0 = __float_as_uint(vr[8 * ni]);
                uint32_t b1 = __float_as_uint(vr[8 * ni + 4 * VS]);
                mma_tf32(o[0][ni], a00, a01, a02, a03, b0, b1);
                mma_tf32(o[1][ni], a10, a11, a12, a13, b0, b1);
            }
        }
        __syncthreads();
    }

    // ---- pair combine (kh=1 publishes; kh=0 merges + writes) ----
    float* Ob = Kst0;            // 128 x 68 (reuse K stages)
    float* Ml = Vst0;            // 128 x 2  (reuse V stages)

    if (kh == 1) {
        #pragma unroll
        for (int ch = 0; ch < 2; ch++) {
            int row0 = 32 * wr + 16 * ch + g;
            int row1 = row0 + 8;
            #pragma unroll
            for (int ni = 0; ni < 8; ni++) {
                int col = 8 * ni + 2 * c;
                *(float2*)(Ob + row0 * 68 + col) =
                    make_float2(o[ch][ni][0], o[ch][ni][1]);
                *(float2*)(Ob + row1 * 68 + col) =
                    make_float2(o[ch][ni][2], o[ch][ni][3]);
            }
            if (c == 0) {
                Ml[row0 * 2 + 0] = m_[ch][0]; Ml[row0 * 2 + 1] = l_[ch][0];
                Ml[row1 * 2 + 0] = m_[ch][1]; Ml[row1 * 2 + 1] = l_[ch][1];
            }
        }
    }
    __syncthreads();

    if (kh == 0) {
        float* ob = out + (size_t)(b * TT + t0) * HD;
        #pragma unroll
        for (int ch = 0; ch < 2; ch++) {
            int row0 = 32 * wr + 16 * ch + g;
            int row1 = row0 + 8;
            float pm0 = Ml[row0 * 2 + 0], pl0 = Ml[row0 * 2 + 1];
            float pm1 = Ml[row1 * 2 + 0], pl1 = Ml[row1 * 2 + 1];
            float M0 = fmaxf(m_[ch][0], pm0), M1 = fmaxf(m_[ch][1], pm1);
            float e0 = ex2(m_[ch][0] - M0), p0 = ex2(pm0 - M0);
            float e1 = ex2(m_[ch][1] - M1), p1 = ex2(pm1 - M1);
            float inv0 = 1.0f / (l_[ch][0] * e0 + pl0 * p0);
            float inv1 = 1.0f / (l_[ch][1] * e1 + pl1 * p1);
            #pragma unroll
            for (int ni = 0; ni < 8; ni++) {
                int col = 8 * ni + 2 * c;
                float2 q0 = *(const float2*)(Ob + row0 * 68 + col);
                float2 q1 = *(const float2*)(Ob + row1 * 68 + col);
                *(float2*)(ob + row0 * HD + col) =
                    make_float2((o[ch][ni][0] * e0 + q0.x * p0) * inv0,
                                (o[ch][ni][1] * e0 + q0.y * p0) * inv0);
                *(float2*)(ob + row1 * HD + col) =
                    make_float2((o[ch][ni][2] * e1 + q1.x * p1) * inv1,
                                (o[ch][ni][3] * e1 + q1.y * p1) * inv1);
            }
        }
    }
}

extern "C" void kernel_launch(void* const* d_in, const int* in_sizes, int n_in,
                              void* d_out, int out_size)
{
    const float* x  = (const float*)d_in[0];
    const float* wq = (const float*)d_in[1];
    const float* wk = (const float*)d_in[2];
    const float* wv = (const float*)d_in[3];
    float* out = (float*)d_out;

    const int qkv_smem = (2 * TM * XS + 2 * 192 * XS) * sizeof(float);
    cudaFuncSetAttribute(qkv_fused, cudaFuncAttributeMaxDynamicSharedMemorySize,
                         qkv_smem);
    cudaFuncSetAttribute(attn_tc, cudaFuncAttributeMaxDynamicSharedMemorySize,
                         ATTN_SMEM);

    wprep<<<192, 256>>>(wq, wk, wv);
    qkv_fused<<<(BB * TT) / TM, 256, qkv_smem>>>(x);
    attn_tc<<<dim3(TT / TM, BB), 256, ATTN_SMEM>>>(out);
}